// round 10
// baseline (speedup 1.0000x reference)
#include <cuda_runtime.h>
#include <cuda_fp16.h>
#include <cuda_bf16.h>
#include <cstdint>

#define N_NODES 100000
#define N_EDGES 1600000
#define HID     128
#define IN_NODE 64
#define IN_EDGE 16
#define NEG_SLOPE 0.01f
#define LN_EPS    1e-5f

// Persistent scratch (no allocations allowed).
__device__ float4 g_H  [(size_t)N_NODES * 32];   // 51.2 MB fp32 h
__device__ float4 g_H0 [(size_t)N_NODES * 32];   // 51.2 MB skip
__device__ float4 g_AGG[(size_t)N_NODES * 32];   // 51.2 MB
__device__ uint2  g_Hh [(size_t)N_NODES * 32];   // 25.6 MB fp16 mirror of h (gather table)
// E in DST-SORTED order, fp16: slot i holds e of the edge at CSR position i.
__device__ uint2  g_E2 [(size_t)N_EDGES * 32];   // 409.6 MB, streamed

// Edge indices normalized to int32.
__device__ int g_src[N_EDGES];
__device__ int g_dst[N_EDGES];
__device__ int g_is32;

// CSR by destination.
__device__ int g_deg[N_NODES];
__device__ int g_rowptr[N_NODES + 1];
__device__ int g_cur[N_NODES];
__device__ int g_epos[N_EDGES];   // edge e -> sorted slot
__device__ int g_esrc[N_EDGES];   // sorted slot -> src node

// ---------------------------------------------------------------------------
// Detect edge_index dtype (int32 vs int64) by OR of odd 32-bit words.
// ---------------------------------------------------------------------------
__global__ void detect_kernel(const int* __restrict__ ei32)
{
    __shared__ int s_or;
    if (threadIdx.x == 0) s_or = 0;
    __syncthreads();
    int v = 0;
    for (int i = threadIdx.x; i < 4096; i += blockDim.x)
        v |= ei32[2 * i + 1];
    atomicOr(&s_or, v);
    __syncthreads();
    if (threadIdx.x == 0) g_is32 = (s_or != 0) ? 1 : 0;
}

// Normalize edge_index into g_src/g_dst; also zero degree counters.
__global__ void convert_kernel(const int* __restrict__ ei32)
{
    int i = blockIdx.x * blockDim.x + threadIdx.x;
    if (i < N_NODES) g_deg[i] = 0;
    if (i >= 2 * N_EDGES) return;
    int v = g_is32 ? ei32[i] : ei32[2 * i];
    if ((unsigned)v >= N_NODES) v = 0;   // safety clamp
    if (i < N_EDGES) g_src[i] = v;
    else             g_dst[i - N_EDGES] = v;
}

__global__ void hist_kernel()
{
    int e = blockIdx.x * blockDim.x + threadIdx.x;
    if (e < N_EDGES) atomicAdd(&g_deg[g_dst[e]], 1);
}

// Single-block exclusive scan of g_deg -> g_rowptr (also copies into g_cur).
__global__ void __launch_bounds__(1024) scan_kernel()
{
    __shared__ int s[1024];
    const int t = threadIdx.x;
    int carry = 0;
    for (int base = 0; base < N_NODES; base += 1024) {
        int idx = base + t;
        int v = (idx < N_NODES) ? g_deg[idx] : 0;
        s[t] = v;
        __syncthreads();
#pragma unroll
        for (int off = 1; off < 1024; off <<= 1) {
            int x = (t >= off) ? s[t - off] : 0;
            __syncthreads();
            s[t] += x;
            __syncthreads();
        }
        int total = s[1023];
        if (idx < N_NODES) {
            int ex = carry + s[t] - v;
            g_rowptr[idx] = ex;
            g_cur[idx]    = ex;
        }
        carry += total;
        __syncthreads();
    }
    if (t == 0) g_rowptr[N_NODES] = carry;
}

// Scatter: assign each edge a slot in dst-sorted order; record src per slot.
__global__ void scatter_kernel()
{
    int e = blockIdx.x * blockDim.x + threadIdx.x;
    if (e >= N_EDGES) return;
    int d = g_dst[e];
    int pos = atomicAdd(&g_cur[d], 1);
    g_epos[e] = pos;
    g_esrc[pos] = g_src[e];
}

// ---------------------------------------------------------------------------
// Edge linear (once): g_E2[epos[e]] = fp16(edge_attr[e] @ W_edge + b_edge).
// One warp per edge; lane owns cols lane*4..+3. Streamed I/O.
// ---------------------------------------------------------------------------
__global__ void __launch_bounds__(256) edge_linear_kernel(
    const float* __restrict__ EA,
    const float* __restrict__ WE,
    const float* __restrict__ BE)
{
    const int lane = threadIdx.x & 31;
    const int warp  = (blockIdx.x * blockDim.x + threadIdx.x) >> 5;
    const int nwarp = (gridDim.x * blockDim.x) >> 5;

    const float4* WE4 = (const float4*)WE;
    float4 wreg[16];
#pragma unroll
    for (int k = 0; k < 16; k++) wreg[k] = WE4[k * 32 + lane];
    const float4 be = ((const float4*)BE)[lane];

    const float4* EA4 = (const float4*)EA;

    for (int e = warp; e < N_EDGES; e += nwarp) {
        float4 ea0 = __ldcs(&EA4[(size_t)e * 4 + 0]);
        float4 ea1 = __ldcs(&EA4[(size_t)e * 4 + 1]);
        float4 ea2 = __ldcs(&EA4[(size_t)e * 4 + 2]);
        float4 ea3 = __ldcs(&EA4[(size_t)e * 4 + 3]);
        int pos = __ldg(&g_epos[e]);
        float ev[16] = { ea0.x, ea0.y, ea0.z, ea0.w,
                         ea1.x, ea1.y, ea1.z, ea1.w,
                         ea2.x, ea2.y, ea2.z, ea2.w,
                         ea3.x, ea3.y, ea3.z, ea3.w };
        float4 acc = be;
#pragma unroll
        for (int k = 0; k < 16; k++) {
            acc.x = fmaf(ev[k], wreg[k].x, acc.x);
            acc.y = fmaf(ev[k], wreg[k].y, acc.y);
            acc.z = fmaf(ev[k], wreg[k].z, acc.z);
            acc.w = fmaf(ev[k], wreg[k].w, acc.w);
        }
        uint2 pk;
        ((__half2*)&pk)[0] = __floats2half2_rn(acc.x, acc.y);
        ((__half2*)&pk)[1] = __floats2half2_rn(acc.z, acc.w);
        __stcs(&g_E2[(size_t)pos * 32 + lane], pk);
    }
}

// ---------------------------------------------------------------------------
// Aggregation (per layer, atomic-free): warp per node.
//   AGG[n] = h[n] + sum_{slot in [rowptr[n],rowptr[n+1])} relu(hh[src] + E2[slot])
// E2 read is fully sequential (.cs); hh gather is L2-resident fp16.
// ---------------------------------------------------------------------------
__global__ void __launch_bounds__(256) aggregate_kernel()
{
    const int lane = threadIdx.x & 31;
    const int n = (blockIdx.x * blockDim.x + threadIdx.x) >> 5;
    if (n >= N_NODES) return;

    float4 acc = g_H[(size_t)n * 32 + lane];
    int i   = __ldg(&g_rowptr[n]);
    const int end = __ldg(&g_rowptr[n + 1]);

    // 2-edge unrolled main loop for MLP
    for (; i + 2 <= end; i += 2) {
        int s0 = __ldg(&g_esrc[i]);
        int s1 = __ldg(&g_esrc[i + 1]);
        uint2 e0 = __ldcs(&g_E2[(size_t)i * 32 + lane]);
        uint2 e1 = __ldcs(&g_E2[(size_t)(i + 1) * 32 + lane]);
        uint2 h0 = g_Hh[(size_t)s0 * 32 + lane];
        uint2 h1 = g_Hh[(size_t)s1 * 32 + lane];

        float2 a0 = __half22float2(__hadd2(((__half2*)&h0)[0], ((__half2*)&e0)[0]));
        float2 b0 = __half22float2(__hadd2(((__half2*)&h0)[1], ((__half2*)&e0)[1]));
        acc.x += fmaxf(a0.x, 0.f); acc.y += fmaxf(a0.y, 0.f);
        acc.z += fmaxf(b0.x, 0.f); acc.w += fmaxf(b0.y, 0.f);

        float2 a1 = __half22float2(__hadd2(((__half2*)&h1)[0], ((__half2*)&e1)[0]));
        float2 b1 = __half22float2(__hadd2(((__half2*)&h1)[1], ((__half2*)&e1)[1]));
        acc.x += fmaxf(a1.x, 0.f); acc.y += fmaxf(a1.y, 0.f);
        acc.z += fmaxf(b1.x, 0.f); acc.w += fmaxf(b1.y, 0.f);
    }
    if (i < end) {
        int s0 = __ldg(&g_esrc[i]);
        uint2 e0 = __ldcs(&g_E2[(size_t)i * 32 + lane]);
        uint2 h0 = g_Hh[(size_t)s0 * 32 + lane];
        float2 a0 = __half22float2(__hadd2(((__half2*)&h0)[0], ((__half2*)&e0)[0]));
        float2 b0 = __half22float2(__hadd2(((__half2*)&h0)[1], ((__half2*)&e0)[1]));
        acc.x += fmaxf(a0.x, 0.f); acc.y += fmaxf(a0.y, 0.f);
        acc.z += fmaxf(b0.x, 0.f); acc.w += fmaxf(b0.y, 0.f);
    }
    g_AGG[(size_t)n * 32 + lane] = acc;
}

// ---------------------------------------------------------------------------
// Node linear: h = X @ W_node + b_node. Writes g_H, g_H0, g_Hh.
// ---------------------------------------------------------------------------
__global__ void __launch_bounds__(256) node_linear_kernel(
    const float* __restrict__ X,
    const float* __restrict__ W,
    const float* __restrict__ B)
{
    __shared__ float As[32][IN_NODE];
    __shared__ float Ws[32][HID];
    const int tx = threadIdx.x, ty = threadIdx.y;
    const int tid = ty * 32 + tx;
    const int row0 = blockIdx.x * 32;

    const float4* X4 = (const float4*)X;
    for (int i = tid; i < 32 * 16; i += 256) {
        int r = i >> 4, c = i & 15;
        ((float4*)&As[r][0])[c] = X4[(size_t)(row0 + r) * 16 + c];
    }

    float4 acc[4];
#pragma unroll
    for (int r = 0; r < 4; r++) acc[r] = make_float4(0.f, 0.f, 0.f, 0.f);

    const float4* W4 = (const float4*)W;
    for (int kk = 0; kk < IN_NODE; kk += 32) {
        __syncthreads();
        for (int i = tid; i < 32 * 32; i += 256) {
            int r = i >> 5, c = i & 31;
            ((float4*)&Ws[r][0])[c] = W4[(size_t)(kk + r) * 32 + c];
        }
        __syncthreads();
#pragma unroll
        for (int k = 0; k < 32; k += 4) {
            float4 w0 = *(const float4*)&Ws[k + 0][tx * 4];
            float4 w1 = *(const float4*)&Ws[k + 1][tx * 4];
            float4 w2 = *(const float4*)&Ws[k + 2][tx * 4];
            float4 w3 = *(const float4*)&Ws[k + 3][tx * 4];
#pragma unroll
            for (int r = 0; r < 4; r++) {
                float4 a = *(const float4*)&As[ty * 4 + r][kk + k];
                acc[r].x = fmaf(a.x, w0.x, acc[r].x);
                acc[r].y = fmaf(a.x, w0.y, acc[r].y);
                acc[r].z = fmaf(a.x, w0.z, acc[r].z);
                acc[r].w = fmaf(a.x, w0.w, acc[r].w);
                acc[r].x = fmaf(a.y, w1.x, acc[r].x);
                acc[r].y = fmaf(a.y, w1.y, acc[r].y);
                acc[r].z = fmaf(a.y, w1.z, acc[r].z);
                acc[r].w = fmaf(a.y, w1.w, acc[r].w);
                acc[r].x = fmaf(a.z, w2.x, acc[r].x);
                acc[r].y = fmaf(a.z, w2.y, acc[r].y);
                acc[r].z = fmaf(a.z, w2.z, acc[r].z);
                acc[r].w = fmaf(a.z, w2.w, acc[r].w);
                acc[r].x = fmaf(a.w, w3.x, acc[r].x);
                acc[r].y = fmaf(a.w, w3.y, acc[r].y);
                acc[r].z = fmaf(a.w, w3.z, acc[r].z);
                acc[r].w = fmaf(a.w, w3.w, acc[r].w);
            }
        }
    }

    float4 b4 = ((const float4*)B)[tx];
#pragma unroll
    for (int r = 0; r < 4; r++) {
        int grow = row0 + ty * 4 + r;
        float4 o = make_float4(acc[r].x + b4.x, acc[r].y + b4.y,
                               acc[r].z + b4.z, acc[r].w + b4.w);
        size_t off = (size_t)grow * 32 + tx;
        g_H[off]  = o;
        g_H0[off] = o;
        uint2 pk;
        ((__half2*)&pk)[0] = __floats2half2_rn(o.x, o.y);
        ((__half2*)&pk)[1] = __floats2half2_rn(o.z, o.w);
        g_Hh[off] = pk;
    }
}

// ---------------------------------------------------------------------------
// Conv GEMM: H = leaky_relu(AGG @ W + b). Writes g_H and fp16 mirror g_Hh.
// ---------------------------------------------------------------------------
__global__ void __launch_bounds__(256) conv_kernel(
    const float* __restrict__ W,
    const float* __restrict__ B)
{
    __shared__ float As[32][HID];
    __shared__ float Ws[32][HID];
    const int tx = threadIdx.x, ty = threadIdx.y;
    const int tid = ty * 32 + tx;
    const int row0 = blockIdx.x * 32;

    for (int i = tid; i < 32 * 32; i += 256) {
        int r = i >> 5, c = i & 31;
        ((float4*)&As[r][0])[c] = g_AGG[(size_t)(row0 + r) * 32 + c];
    }

    float4 acc[4];
#pragma unroll
    for (int r = 0; r < 4; r++) acc[r] = make_float4(0.f, 0.f, 0.f, 0.f);

    const float4* W4 = (const float4*)W;
    for (int kk = 0; kk < HID; kk += 32) {
        __syncthreads();
        for (int i = tid; i < 32 * 32; i += 256) {
            int r = i >> 5, c = i & 31;
            ((float4*)&Ws[r][0])[c] = W4[(size_t)(kk + r) * 32 + c];
        }
        __syncthreads();
#pragma unroll
        for (int k = 0; k < 32; k += 4) {
            float4 w0 = *(const float4*)&Ws[k + 0][tx * 4];
            float4 w1 = *(const float4*)&Ws[k + 1][tx * 4];
            float4 w2 = *(const float4*)&Ws[k + 2][tx * 4];
            float4 w3 = *(const float4*)&Ws[k + 3][tx * 4];
#pragma unroll
            for (int r = 0; r < 4; r++) {
                float4 a = *(const float4*)&As[ty * 4 + r][kk + k];
                acc[r].x = fmaf(a.x, w0.x, acc[r].x);
                acc[r].y = fmaf(a.x, w0.y, acc[r].y);
                acc[r].z = fmaf(a.x, w0.z, acc[r].z);
                acc[r].w = fmaf(a.x, w0.w, acc[r].w);
                acc[r].x = fmaf(a.y, w1.x, acc[r].x);
                acc[r].y = fmaf(a.y, w1.y, acc[r].y);
                acc[r].z = fmaf(a.y, w1.z, acc[r].z);
                acc[r].w = fmaf(a.y, w1.w, acc[r].w);
                acc[r].x = fmaf(a.z, w2.x, acc[r].x);
                acc[r].y = fmaf(a.z, w2.y, acc[r].y);
                acc[r].z = fmaf(a.z, w2.z, acc[r].z);
                acc[r].w = fmaf(a.z, w2.w, acc[r].w);
                acc[r].x = fmaf(a.w, w3.x, acc[r].x);
                acc[r].y = fmaf(a.w, w3.y, acc[r].y);
                acc[r].z = fmaf(a.w, w3.z, acc[r].z);
                acc[r].w = fmaf(a.w, w3.w, acc[r].w);
            }
        }
    }

    float4 b4 = ((const float4*)B)[tx];
#pragma unroll
    for (int r = 0; r < 4; r++) {
        int grow = row0 + ty * 4 + r;
        float ox = acc[r].x + b4.x;
        float oy = acc[r].y + b4.y;
        float oz = acc[r].z + b4.z;
        float ow = acc[r].w + b4.w;
        ox = (ox >= 0.f) ? ox : NEG_SLOPE * ox;
        oy = (oy >= 0.f) ? oy : NEG_SLOPE * oy;
        oz = (oz >= 0.f) ? oz : NEG_SLOPE * oz;
        ow = (ow >= 0.f) ? ow : NEG_SLOPE * ow;
        float4 o = make_float4(ox, oy, oz, ow);
        size_t off = (size_t)grow * 32 + tx;
        g_H[off] = o;
        uint2 pk;
        ((__half2*)&pk)[0] = __floats2half2_rn(o.x, o.y);
        ((__half2*)&pk)[1] = __floats2half2_rn(o.z, o.w);
        g_Hh[off] = pk;
    }
}

// ---------------------------------------------------------------------------
// Head: y = (H0 + H) @ W_head + b; out = LayerNorm(y)*gamma + beta
// ---------------------------------------------------------------------------
__global__ void __launch_bounds__(256) head_kernel(
    const float* __restrict__ W,
    const float* __restrict__ B,
    const float* __restrict__ G,
    const float* __restrict__ BT,
    float* __restrict__ OUT)
{
    __shared__ float As[32][HID];
    __shared__ float Ws[32][HID];
    const int tx = threadIdx.x, ty = threadIdx.y;
    const int tid = ty * 32 + tx;
    const int row0 = blockIdx.x * 32;

    for (int i = tid; i < 32 * 32; i += 256) {
        int r = i >> 5, c = i & 31;
        size_t off = (size_t)(row0 + r) * 32 + c;
        float4 a = g_H0[off];
        float4 b = g_H[off];
        ((float4*)&As[r][0])[c] =
            make_float4(a.x + b.x, a.y + b.y, a.z + b.z, a.w + b.w);
    }

    float4 acc[4];
#pragma unroll
    for (int r = 0; r < 4; r++) acc[r] = make_float4(0.f, 0.f, 0.f, 0.f);

    const float4* W4 = (const float4*)W;
    for (int kk = 0; kk < HID; kk += 32) {
        __syncthreads();
        for (int i = tid; i < 32 * 32; i += 256) {
            int r = i >> 5, c = i & 31;
            ((float4*)&Ws[r][0])[c] = W4[(size_t)(kk + r) * 32 + c];
        }
        __syncthreads();
#pragma unroll
        for (int k = 0; k < 32; k += 4) {
            float4 w0 = *(const float4*)&Ws[k + 0][tx * 4];
            float4 w1 = *(const float4*)&Ws[k + 1][tx * 4];
            float4 w2 = *(const float4*)&Ws[k + 2][tx * 4];
            float4 w3 = *(const float4*)&Ws[k + 3][tx * 4];
#pragma unroll
            for (int r = 0; r < 4; r++) {
                float4 a = *(const float4*)&As[ty * 4 + r][kk + k];
                acc[r].x = fmaf(a.x, w0.x, acc[r].x);
                acc[r].y = fmaf(a.x, w0.y, acc[r].y);
                acc[r].z = fmaf(a.x, w0.z, acc[r].z);
                acc[r].w = fmaf(a.x, w0.w, acc[r].w);
                acc[r].x = fmaf(a.y, w1.x, acc[r].x);
                acc[r].y = fmaf(a.y, w1.y, acc[r].y);
                acc[r].z = fmaf(a.y, w1.z, acc[r].z);
                acc[r].w = fmaf(a.y, w1.w, acc[r].w);
                acc[r].x = fmaf(a.z, w2.x, acc[r].x);
                acc[r].y = fmaf(a.z, w2.y, acc[r].y);
                acc[r].z = fmaf(a.z, w2.z, acc[r].z);
                acc[r].w = fmaf(a.z, w2.w, acc[r].w);
                acc[r].x = fmaf(a.w, w3.x, acc[r].x);
                acc[r].y = fmaf(a.w, w3.y, acc[r].y);
                acc[r].z = fmaf(a.w, w3.z, acc[r].z);
                acc[r].w = fmaf(a.w, w3.w, acc[r].w);
            }
        }
    }

    float4 b4 = ((const float4*)B)[tx];
    float4 g4 = ((const float4*)G)[tx];
    float4 t4 = ((const float4*)BT)[tx];
    float4* OUT4 = (float4*)OUT;

#pragma unroll
    for (int r = 0; r < 4; r++) {
        int grow = row0 + ty * 4 + r;
        float yx = acc[r].x + b4.x;
        float yy = acc[r].y + b4.y;
        float yz = acc[r].z + b4.z;
        float yw = acc[r].w + b4.w;
        float s = yx + yy + yz + yw;
#pragma unroll
        for (int off = 16; off > 0; off >>= 1)
            s += __shfl_xor_sync(0xffffffffu, s, off);
        float mu = s * (1.0f / HID);
        float dx = yx - mu, dy = yy - mu, dz = yz - mu, dw = yw - mu;
        float q = dx * dx + dy * dy + dz * dz + dw * dw;
#pragma unroll
        for (int off = 16; off > 0; off >>= 1)
            q += __shfl_xor_sync(0xffffffffu, q, off);
        float inv = rsqrtf(q * (1.0f / HID) + LN_EPS);
        float4 o = make_float4(dx * inv * g4.x + t4.x,
                               dy * inv * g4.y + t4.y,
                               dz * inv * g4.z + t4.z,
                               dw * inv * g4.w + t4.w);
        OUT4[(size_t)grow * 32 + tx] = o;
    }
}

// ---------------------------------------------------------------------------
extern "C" void kernel_launch(void* const* d_in, const int* in_sizes, int n_in,
                              void* d_out, int out_size)
{
    const float* x   = (const float*)d_in[0];
    const float* ea  = (const float*)d_in[1];
    const int*   ei  = (const int*)d_in[2];
    const float* Wn  = (const float*)d_in[3];
    const float* bn  = (const float*)d_in[4];
    const float* We  = (const float*)d_in[5];
    const float* be  = (const float*)d_in[6];
    const float* Wc  = (const float*)d_in[7];
    const float* bc  = (const float*)d_in[8];
    const float* Wh  = (const float*)d_in[9];
    const float* bh  = (const float*)d_in[10];
    const float* gam = (const float*)d_in[11];
    const float* bet = (const float*)d_in[12];
    float* out = (float*)d_out;

    dim3 blk(32, 8);
    const int gemm_grid = N_NODES / 32;            // 3125
    const int agg_grid  = (N_NODES * 32 + 255) / 256;  // warp per node

    // CSR build (once)
    detect_kernel<<<1, 256>>>(ei);
    convert_kernel<<<(2 * N_EDGES + 255) / 256, 256>>>(ei);
    hist_kernel<<<(N_EDGES + 255) / 256, 256>>>();
    scan_kernel<<<1, 1024>>>();
    scatter_kernel<<<(N_EDGES + 255) / 256, 256>>>();

    edge_linear_kernel<<<2048, 256>>>(ea, We, be);
    node_linear_kernel<<<gemm_grid, blk>>>(x, Wn, bn);
    for (int l = 0; l < 3; l++) {
        aggregate_kernel<<<agg_grid, 256>>>();
        conv_kernel<<<gemm_grid, blk>>>(Wc + (size_t)l * HID * HID, bc + l * HID);
    }
    head_kernel<<<gemm_grid, blk>>>(Wh, bh, gam, bet, out);
}

// round 12
// speedup vs baseline: 1.1109x; 1.1109x over previous
#include <cuda_runtime.h>
#include <cuda_fp16.h>
#include <cuda_bf16.h>
#include <cstdint>

#define N_NODES 100000
#define N_EDGES 1600000
#define HID     128
#define IN_NODE 64
#define IN_EDGE 16
#define NEG_SLOPE 0.01f
#define LN_EPS    1e-5f

#define SCAN_TILE 1024
#define N_TILES   ((N_NODES + SCAN_TILE - 1) / SCAN_TILE)   // 98

// Persistent scratch (no allocations allowed).
__device__ float4 g_H  [(size_t)N_NODES * 32];   // 51.2 MB fp32 h
__device__ float4 g_H0 [(size_t)N_NODES * 32];   // 51.2 MB skip
__device__ float4 g_AGG[(size_t)N_NODES * 32];   // 51.2 MB
__device__ uint2  g_Hh [(size_t)N_NODES * 32];   // 25.6 MB fp16 mirror of h
// E in DST-SORTED order, fp16: slot i holds e of the edge at CSR position i.
__device__ uint2  g_E2 [(size_t)N_EDGES * 32];   // 409.6 MB, streamed

// Edge indices normalized to int32.
__device__ int g_src[N_EDGES];
__device__ int g_dst[N_EDGES];
__device__ int g_is32;

// CSR by destination.
__device__ int g_deg[N_NODES];
__device__ int g_rowptr[N_NODES + 1];
__device__ int g_cur[N_NODES];
__device__ int g_epos[N_EDGES];   // edge e -> sorted slot
__device__ int g_esrc[N_EDGES];   // sorted slot -> src node
__device__ int g_bsum[N_TILES];
__device__ int g_boff[N_TILES];

// ---------------------------------------------------------------------------
// Detect edge_index dtype (int32 vs int64) by OR of odd 32-bit words.
// ---------------------------------------------------------------------------
__global__ void detect_kernel(const int* __restrict__ ei32)
{
    __shared__ int s_or;
    if (threadIdx.x == 0) s_or = 0;
    __syncthreads();
    int v = 0;
    for (int i = threadIdx.x; i < 4096; i += blockDim.x)
        v |= ei32[2 * i + 1];
    atomicOr(&s_or, v);
    __syncthreads();
    if (threadIdx.x == 0) g_is32 = (s_or != 0) ? 1 : 0;
}

// Normalize edge_index into g_src/g_dst; also zero degree counters.
__global__ void convert_kernel(const int* __restrict__ ei32)
{
    int i = blockIdx.x * blockDim.x + threadIdx.x;
    if (i < N_NODES) g_deg[i] = 0;
    if (i >= 2 * N_EDGES) return;
    int v = g_is32 ? ei32[i] : ei32[2 * i];
    if ((unsigned)v >= N_NODES) v = 0;   // safety clamp
    if (i < N_EDGES) g_src[i] = v;
    else             g_dst[i - N_EDGES] = v;
}

__global__ void hist_kernel()
{
    int e = blockIdx.x * blockDim.x + threadIdx.x;
    if (e < N_EDGES) atomicAdd(&g_deg[g_dst[e]], 1);
}

// ---------------------------------------------------------------------------
// Parallel exclusive scan of g_deg -> g_rowptr (3 cheap kernels).
// ---------------------------------------------------------------------------
// 1) Per-tile inclusive scan (one block per tile); tile total to g_bsum.
__global__ void __launch_bounds__(SCAN_TILE) scan_partial_kernel()
{
    __shared__ int s[SCAN_TILE];
    const int t = threadIdx.x;
    const int idx = blockIdx.x * SCAN_TILE + t;
    int v = (idx < N_NODES) ? g_deg[idx] : 0;
    s[t] = v;
    __syncthreads();
#pragma unroll
    for (int off = 1; off < SCAN_TILE; off <<= 1) {
        int x = (t >= off) ? s[t - off] : 0;
        __syncthreads();
        s[t] += x;
        __syncthreads();
    }
    if (idx < N_NODES) g_rowptr[idx] = s[t];   // inclusive, tile-local
    if (t == SCAN_TILE - 1) g_bsum[blockIdx.x] = s[t];
}

// 2) Serial scan of the 98 tile sums (trivial).
__global__ void scan_bsums_kernel()
{
    if (threadIdx.x == 0) {
        int acc = 0;
        for (int b = 0; b < N_TILES; b++) { g_boff[b] = acc; acc += g_bsum[b]; }
    }
}

// 3) Finalize: exclusive rowptr (+tile offset), copy to g_cur.
__global__ void scan_finalize_kernel()
{
    int idx = blockIdx.x * blockDim.x + threadIdx.x;
    if (idx >= N_NODES) return;
    int ex = g_rowptr[idx] - g_deg[idx] + g_boff[idx / SCAN_TILE];
    g_rowptr[idx] = ex;
    g_cur[idx]    = ex;
    if (idx == 0) g_rowptr[N_NODES] = N_EDGES;
}

// Scatter: assign each edge a slot in dst-sorted order; record src per slot.
__global__ void scatter_kernel()
{
    int e = blockIdx.x * blockDim.x + threadIdx.x;
    if (e >= N_EDGES) return;
    int d = g_dst[e];
    int pos = atomicAdd(&g_cur[d], 1);
    g_epos[e] = pos;
    g_esrc[pos] = g_src[e];
}

// ---------------------------------------------------------------------------
// Edge linear (once): g_E2[epos[e]] = fp16(edge_attr[e] @ W_edge + b_edge).
// One warp per edge; lane owns cols lane*4..+3. Streamed I/O.
// ---------------------------------------------------------------------------
__global__ void __launch_bounds__(256) edge_linear_kernel(
    const float* __restrict__ EA,
    const float* __restrict__ WE,
    const float* __restrict__ BE)
{
    const int lane = threadIdx.x & 31;
    const int warp  = (blockIdx.x * blockDim.x + threadIdx.x) >> 5;
    const int nwarp = (gridDim.x * blockDim.x) >> 5;

    const float4* WE4 = (const float4*)WE;
    float4 wreg[16];
#pragma unroll
    for (int k = 0; k < 16; k++) wreg[k] = WE4[k * 32 + lane];
    const float4 be = ((const float4*)BE)[lane];

    const float4* EA4 = (const float4*)EA;

    for (int e = warp; e < N_EDGES; e += nwarp) {
        float4 ea0 = __ldcs(&EA4[(size_t)e * 4 + 0]);
        float4 ea1 = __ldcs(&EA4[(size_t)e * 4 + 1]);
        float4 ea2 = __ldcs(&EA4[(size_t)e * 4 + 2]);
        float4 ea3 = __ldcs(&EA4[(size_t)e * 4 + 3]);
        int pos = __ldg(&g_epos[e]);
        float ev[16] = { ea0.x, ea0.y, ea0.z, ea0.w,
                         ea1.x, ea1.y, ea1.z, ea1.w,
                         ea2.x, ea2.y, ea2.z, ea2.w,
                         ea3.x, ea3.y, ea3.z, ea3.w };
        float4 acc = be;
#pragma unroll
        for (int k = 0; k < 16; k++) {
            acc.x = fmaf(ev[k], wreg[k].x, acc.x);
            acc.y = fmaf(ev[k], wreg[k].y, acc.y);
            acc.z = fmaf(ev[k], wreg[k].z, acc.z);
            acc.w = fmaf(ev[k], wreg[k].w, acc.w);
        }
        uint2 pk;
        ((__half2*)&pk)[0] = __floats2half2_rn(acc.x, acc.y);
        ((__half2*)&pk)[1] = __floats2half2_rn(acc.z, acc.w);
        __stcs(&g_E2[(size_t)pos * 32 + lane], pk);
    }
}

// ---------------------------------------------------------------------------
// Aggregation (per layer, atomic-free): warp per node.
//   AGG[n] = h[n] + sum relu(hh[src] + E2[slot])
// 4-edge unroll with front-batched loads (esrc -> E2 -> Hh) for MLP.
// ---------------------------------------------------------------------------
__global__ void __launch_bounds__(256) aggregate_kernel()
{
    const int lane = threadIdx.x & 31;
    const int n = (blockIdx.x * blockDim.x + threadIdx.x) >> 5;
    if (n >= N_NODES) return;

    float4 acc = g_H[(size_t)n * 32 + lane];
    int i   = __ldg(&g_rowptr[n]);
    const int end = __ldg(&g_rowptr[n + 1]);

    for (; i + 4 <= end; i += 4) {
        int s0 = __ldg(&g_esrc[i + 0]);
        int s1 = __ldg(&g_esrc[i + 1]);
        int s2 = __ldg(&g_esrc[i + 2]);
        int s3 = __ldg(&g_esrc[i + 3]);
        uint2 e0 = __ldcs(&g_E2[(size_t)(i + 0) * 32 + lane]);
        uint2 e1 = __ldcs(&g_E2[(size_t)(i + 1) * 32 + lane]);
        uint2 e2 = __ldcs(&g_E2[(size_t)(i + 2) * 32 + lane]);
        uint2 e3 = __ldcs(&g_E2[(size_t)(i + 3) * 32 + lane]);
        uint2 h0 = g_Hh[(size_t)s0 * 32 + lane];
        uint2 h1 = g_Hh[(size_t)s1 * 32 + lane];
        uint2 h2 = g_Hh[(size_t)s2 * 32 + lane];
        uint2 h3 = g_Hh[(size_t)s3 * 32 + lane];

        float2 a, b;
        a = __half22float2(__hadd2(((__half2*)&h0)[0], ((__half2*)&e0)[0]));
        b = __half22float2(__hadd2(((__half2*)&h0)[1], ((__half2*)&e0)[1]));
        acc.x += fmaxf(a.x, 0.f); acc.y += fmaxf(a.y, 0.f);
        acc.z += fmaxf(b.x, 0.f); acc.w += fmaxf(b.y, 0.f);
        a = __half22float2(__hadd2(((__half2*)&h1)[0], ((__half2*)&e1)[0]));
        b = __half22float2(__hadd2(((__half2*)&h1)[1], ((__half2*)&e1)[1]));
        acc.x += fmaxf(a.x, 0.f); acc.y += fmaxf(a.y, 0.f);
        acc.z += fmaxf(b.x, 0.f); acc.w += fmaxf(b.y, 0.f);
        a = __half22float2(__hadd2(((__half2*)&h2)[0], ((__half2*)&e2)[0]));
        b = __half22float2(__hadd2(((__half2*)&h2)[1], ((__half2*)&e2)[1]));
        acc.x += fmaxf(a.x, 0.f); acc.y += fmaxf(a.y, 0.f);
        acc.z += fmaxf(b.x, 0.f); acc.w += fmaxf(b.y, 0.f);
        a = __half22float2(__hadd2(((__half2*)&h3)[0], ((__half2*)&e3)[0]));
        b = __half22float2(__hadd2(((__half2*)&h3)[1], ((__half2*)&e3)[1]));
        acc.x += fmaxf(a.x, 0.f); acc.y += fmaxf(a.y, 0.f);
        acc.z += fmaxf(b.x, 0.f); acc.w += fmaxf(b.y, 0.f);
    }
    for (; i < end; i++) {
        int s0 = __ldg(&g_esrc[i]);
        uint2 e0 = __ldcs(&g_E2[(size_t)i * 32 + lane]);
        uint2 h0 = g_Hh[(size_t)s0 * 32 + lane];
        float2 a = __half22float2(__hadd2(((__half2*)&h0)[0], ((__half2*)&e0)[0]));
        float2 b = __half22float2(__hadd2(((__half2*)&h0)[1], ((__half2*)&e0)[1]));
        acc.x += fmaxf(a.x, 0.f); acc.y += fmaxf(a.y, 0.f);
        acc.z += fmaxf(b.x, 0.f); acc.w += fmaxf(b.y, 0.f);
    }
    g_AGG[(size_t)n * 32 + lane] = acc;
}

// ---------------------------------------------------------------------------
// Node linear: h = X @ W_node + b_node. Writes g_H, g_H0, g_Hh.
// ---------------------------------------------------------------------------
__global__ void __launch_bounds__(256) node_linear_kernel(
    const float* __restrict__ X,
    const float* __restrict__ W,
    const float* __restrict__ B)
{
    __shared__ float As[32][IN_NODE];
    __shared__ float Ws[32][HID];
    const int tx = threadIdx.x, ty = threadIdx.y;
    const int tid = ty * 32 + tx;
    const int row0 = blockIdx.x * 32;

    const float4* X4 = (const float4*)X;
    for (int i = tid; i < 32 * 16; i += 256) {
        int r = i >> 4, c = i & 15;
        ((float4*)&As[r][0])[c] = X4[(size_t)(row0 + r) * 16 + c];
    }

    float4 acc[4];
#pragma unroll
    for (int r = 0; r < 4; r++) acc[r] = make_float4(0.f, 0.f, 0.f, 0.f);

    const float4* W4 = (const float4*)W;
    for (int kk = 0; kk < IN_NODE; kk += 32) {
        __syncthreads();
        for (int i = tid; i < 32 * 32; i += 256) {
            int r = i >> 5, c = i & 31;
            ((float4*)&Ws[r][0])[c] = W4[(size_t)(kk + r) * 32 + c];
        }
        __syncthreads();
#pragma unroll
        for (int k = 0; k < 32; k += 4) {
            float4 w0 = *(const float4*)&Ws[k + 0][tx * 4];
            float4 w1 = *(const float4*)&Ws[k + 1][tx * 4];
            float4 w2 = *(const float4*)&Ws[k + 2][tx * 4];
            float4 w3 = *(const float4*)&Ws[k + 3][tx * 4];
#pragma unroll
            for (int r = 0; r < 4; r++) {
                float4 a = *(const float4*)&As[ty * 4 + r][kk + k];
                acc[r].x = fmaf(a.x, w0.x, acc[r].x);
                acc[r].y = fmaf(a.x, w0.y, acc[r].y);
                acc[r].z = fmaf(a.x, w0.z, acc[r].z);
                acc[r].w = fmaf(a.x, w0.w, acc[r].w);
                acc[r].x = fmaf(a.y, w1.x, acc[r].x);
                acc[r].y = fmaf(a.y, w1.y, acc[r].y);
                acc[r].z = fmaf(a.y, w1.z, acc[r].z);
                acc[r].w = fmaf(a.y, w1.w, acc[r].w);
                acc[r].x = fmaf(a.z, w2.x, acc[r].x);
                acc[r].y = fmaf(a.z, w2.y, acc[r].y);
                acc[r].z = fmaf(a.z, w2.z, acc[r].z);
                acc[r].w = fmaf(a.z, w2.w, acc[r].w);
                acc[r].x = fmaf(a.w, w3.x, acc[r].x);
                acc[r].y = fmaf(a.w, w3.y, acc[r].y);
                acc[r].z = fmaf(a.w, w3.z, acc[r].z);
                acc[r].w = fmaf(a.w, w3.w, acc[r].w);
            }
        }
    }

    float4 b4 = ((const float4*)B)[tx];
#pragma unroll
    for (int r = 0; r < 4; r++) {
        int grow = row0 + ty * 4 + r;
        float4 o = make_float4(acc[r].x + b4.x, acc[r].y + b4.y,
                               acc[r].z + b4.z, acc[r].w + b4.w);
        size_t off = (size_t)grow * 32 + tx;
        g_H[off]  = o;
        g_H0[off] = o;
        uint2 pk;
        ((__half2*)&pk)[0] = __floats2half2_rn(o.x, o.y);
        ((__half2*)&pk)[1] = __floats2half2_rn(o.z, o.w);
        g_Hh[off] = pk;
    }
}

// ---------------------------------------------------------------------------
// Conv GEMM: H = leaky_relu(AGG @ W + b). Writes g_H and fp16 mirror g_Hh.
// ---------------------------------------------------------------------------
__global__ void __launch_bounds__(256) conv_kernel(
    const float* __restrict__ W,
    const float* __restrict__ B)
{
    __shared__ float As[32][HID];
    __shared__ float Ws[32][HID];
    const int tx = threadIdx.x, ty = threadIdx.y;
    const int tid = ty * 32 + tx;
    const int row0 = blockIdx.x * 32;

    for (int i = tid; i < 32 * 32; i += 256) {
        int r = i >> 5, c = i & 31;
        ((float4*)&As[r][0])[c] = g_AGG[(size_t)(row0 + r) * 32 + c];
    }

    float4 acc[4];
#pragma unroll
    for (int r = 0; r < 4; r++) acc[r] = make_float4(0.f, 0.f, 0.f, 0.f);

    const float4* W4 = (const float4*)W;
    for (int kk = 0; kk < HID; kk += 32) {
        __syncthreads();
        for (int i = tid; i < 32 * 32; i += 256) {
            int r = i >> 5, c = i & 31;
            ((float4*)&Ws[r][0])[c] = W4[(size_t)(kk + r) * 32 + c];
        }
        __syncthreads();
#pragma unroll
        for (int k = 0; k < 32; k += 4) {
            float4 w0 = *(const float4*)&Ws[k + 0][tx * 4];
            float4 w1 = *(const float4*)&Ws[k + 1][tx * 4];
            float4 w2 = *(const float4*)&Ws[k + 2][tx * 4];
            float4 w3 = *(const float4*)&Ws[k + 3][tx * 4];
#pragma unroll
            for (int r = 0; r < 4; r++) {
                float4 a = *(const float4*)&As[ty * 4 + r][kk + k];
                acc[r].x = fmaf(a.x, w0.x, acc[r].x);
                acc[r].y = fmaf(a.x, w0.y, acc[r].y);
                acc[r].z = fmaf(a.x, w0.z, acc[r].z);
                acc[r].w = fmaf(a.x, w0.w, acc[r].w);
                acc[r].x = fmaf(a.y, w1.x, acc[r].x);
                acc[r].y = fmaf(a.y, w1.y, acc[r].y);
                acc[r].z = fmaf(a.y, w1.z, acc[r].z);
                acc[r].w = fmaf(a.y, w1.w, acc[r].w);
                acc[r].x = fmaf(a.z, w2.x, acc[r].x);
                acc[r].y = fmaf(a.z, w2.y, acc[r].y);
                acc[r].z = fmaf(a.z, w2.z, acc[r].z);
                acc[r].w = fmaf(a.z, w2.w, acc[r].w);
                acc[r].x = fmaf(a.w, w3.x, acc[r].x);
                acc[r].y = fmaf(a.w, w3.y, acc[r].y);
                acc[r].z = fmaf(a.w, w3.z, acc[r].z);
                acc[r].w = fmaf(a.w, w3.w, acc[r].w);
            }
        }
    }

    float4 b4 = ((const float4*)B)[tx];
#pragma unroll
    for (int r = 0; r < 4; r++) {
        int grow = row0 + ty * 4 + r;
        float ox = acc[r].x + b4.x;
        float oy = acc[r].y + b4.y;
        float oz = acc[r].z + b4.z;
        float ow = acc[r].w + b4.w;
        ox = (ox >= 0.f) ? ox : NEG_SLOPE * ox;
        oy = (oy >= 0.f) ? oy : NEG_SLOPE * oy;
        oz = (oz >= 0.f) ? oz : NEG_SLOPE * oz;
        ow = (ow >= 0.f) ? ow : NEG_SLOPE * ow;
        float4 o = make_float4(ox, oy, oz, ow);
        size_t off = (size_t)grow * 32 + tx;
        g_H[off] = o;
        uint2 pk;
        ((__half2*)&pk)[0] = __floats2half2_rn(o.x, o.y);
        ((__half2*)&pk)[1] = __floats2half2_rn(o.z, o.w);
        g_Hh[off] = pk;
    }
}

// ---------------------------------------------------------------------------
// Head: y = (H0 + H) @ W_head + b; out = LayerNorm(y)*gamma + beta
// ---------------------------------------------------------------------------
__global__ void __launch_bounds__(256) head_kernel(
    const float* __restrict__ W,
    const float* __restrict__ B,
    const float* __restrict__ G,
    const float* __restrict__ BT,
    float* __restrict__ OUT)
{
    __shared__ float As[32][HID];
    __shared__ float Ws[32][HID];
    const int tx = threadIdx.x, ty = threadIdx.y;
    const int tid = ty * 32 + tx;
    const int row0 = blockIdx.x * 32;

    for (int i = tid; i < 32 * 32; i += 256) {
        int r = i >> 5, c = i & 31;
        size_t off = (size_t)(row0 + r) * 32 + c;
        float4 a = g_H0[off];
        float4 b = g_H[off];
        ((float4*)&As[r][0])[c] =
            make_float4(a.x + b.x, a.y + b.y, a.z + b.z, a.w + b.w);
    }

    float4 acc[4];
#pragma unroll
    for (int r = 0; r < 4; r++) acc[r] = make_float4(0.f, 0.f, 0.f, 0.f);

    const float4* W4 = (const float4*)W;
    for (int kk = 0; kk < HID; kk += 32) {
        __syncthreads();
        for (int i = tid; i < 32 * 32; i += 256) {
            int r = i >> 5, c = i & 31;
            ((float4*)&Ws[r][0])[c] = W4[(size_t)(kk + r) * 32 + c];
        }
        __syncthreads();
#pragma unroll
        for (int k = 0; k < 32; k += 4) {
            float4 w0 = *(const float4*)&Ws[k + 0][tx * 4];
            float4 w1 = *(const float4*)&Ws[k + 1][tx * 4];
            float4 w2 = *(const float4*)&Ws[k + 2][tx * 4];
            float4 w3 = *(const float4*)&Ws[k + 3][tx * 4];
#pragma unroll
            for (int r = 0; r < 4; r++) {
                float4 a = *(const float4*)&As[ty * 4 + r][kk + k];
                acc[r].x = fmaf(a.x, w0.x, acc[r].x);
                acc[r].y = fmaf(a.x, w0.y, acc[r].y);
                acc[r].z = fmaf(a.x, w0.z, acc[r].z);
                acc[r].w = fmaf(a.x, w0.w, acc[r].w);
                acc[r].x = fmaf(a.y, w1.x, acc[r].x);
                acc[r].y = fmaf(a.y, w1.y, acc[r].y);
                acc[r].z = fmaf(a.y, w1.z, acc[r].z);
                acc[r].w = fmaf(a.y, w1.w, acc[r].w);
                acc[r].x = fmaf(a.z, w2.x, acc[r].x);
                acc[r].y = fmaf(a.z, w2.y, acc[r].y);
                acc[r].z = fmaf(a.z, w2.z, acc[r].z);
                acc[r].w = fmaf(a.z, w2.w, acc[r].w);
                acc[r].x = fmaf(a.w, w3.x, acc[r].x);
                acc[r].y = fmaf(a.w, w3.y, acc[r].y);
                acc[r].z = fmaf(a.w, w3.z, acc[r].z);
                acc[r].w = fmaf(a.w, w3.w, acc[r].w);
            }
        }
    }

    float4 b4 = ((const float4*)B)[tx];
    float4 g4 = ((const float4*)G)[tx];
    float4 t4 = ((const float4*)BT)[tx];
    float4* OUT4 = (float4*)OUT;

#pragma unroll
    for (int r = 0; r < 4; r++) {
        int grow = row0 + ty * 4 + r;
        float yx = acc[r].x + b4.x;
        float yy = acc[r].y + b4.y;
        float yz = acc[r].z + b4.z;
        float yw = acc[r].w + b4.w;
        float s = yx + yy + yz + yw;
#pragma unroll
        for (int off = 16; off > 0; off >>= 1)
            s += __shfl_xor_sync(0xffffffffu, s, off);
        float mu = s * (1.0f / HID);
        float dx = yx - mu, dy = yy - mu, dz = yz - mu, dw = yw - mu;
        float q = dx * dx + dy * dy + dz * dz + dw * dw;
#pragma unroll
        for (int off = 16; off > 0; off >>= 1)
            q += __shfl_xor_sync(0xffffffffu, q, off);
        float inv = rsqrtf(q * (1.0f / HID) + LN_EPS);
        float4 o = make_float4(dx * inv * g4.x + t4.x,
                               dy * inv * g4.y + t4.y,
                               dz * inv * g4.z + t4.z,
                               dw * inv * g4.w + t4.w);
        OUT4[(size_t)grow * 32 + tx] = o;
    }
}

// ---------------------------------------------------------------------------
extern "C" void kernel_launch(void* const* d_in, const int* in_sizes, int n_in,
                              void* d_out, int out_size)
{
    const float* x   = (const float*)d_in[0];
    const float* ea  = (const float*)d_in[1];
    const int*   ei  = (const int*)d_in[2];
    const float* Wn  = (const float*)d_in[3];
    const float* bn  = (const float*)d_in[4];
    const float* We  = (const float*)d_in[5];
    const float* be  = (const float*)d_in[6];
    const float* Wc  = (const float*)d_in[7];
    const float* bc  = (const float*)d_in[8];
    const float* Wh  = (const float*)d_in[9];
    const float* bh  = (const float*)d_in[10];
    const float* gam = (const float*)d_in[11];
    const float* bet = (const float*)d_in[12];
    float* out = (float*)d_out;

    dim3 blk(32, 8);
    const int gemm_grid = N_NODES / 32;                 // 3125
    const int agg_grid  = (N_NODES * 32 + 255) / 256;   // warp per node

    // CSR build (once)
    detect_kernel<<<1, 256>>>(ei);
    convert_kernel<<<(2 * N_EDGES + 255) / 256, 256>>>(ei);
    hist_kernel<<<(N_EDGES + 255) / 256, 256>>>();
    scan_partial_kernel<<<N_TILES, SCAN_TILE>>>();
    scan_bsums_kernel<<<1, 32>>>();
    scan_finalize_kernel<<<(N_NODES + 255) / 256, 256>>>();
    scatter_kernel<<<(N_EDGES + 255) / 256, 256>>>();

    edge_linear_kernel<<<2048, 256>>>(ea, We, be);
    node_linear_kernel<<<gemm_grid, blk>>>(x, Wn, bn);
    for (int l = 0; l < 3; l++) {
        aggregate_kernel<<<agg_grid, 256>>>();
        conv_kernel<<<gemm_grid, blk>>>(Wc + (size_t)l * HID * HID, bc + l * HID);
    }
    head_kernel<<<gemm_grid, blk>>>(Wh, bh, gam, bet, out);
}